// round 2
// baseline (speedup 1.0000x reference)
#include <cuda_runtime.h>
#include <cuda_fp16.h>
#include <cstdint>

// ---------------- problem dims (fixed) ----------------
#define MDIM 8192
#define NDIM 4096
#define KDIM 4096
#define GROUPS 32
#define BLOB  64

// ---------------- GEMM tiling ----------------
#define BM 128
#define BN 128
#define BK 64            // halves per k-tile (128 bytes per row)
#define STAGES 4
#define GEMM_THREADS 256
#define KTILES (KDIM / BK)            // 64
#define STAGE_BYTES 32768             // A 16KB + B 16KB
#define SMEM_TOTAL (STAGES * STAGE_BYTES)

// fp16 scratch (static device globals; no allocations)
__device__ __half d_Ah[(size_t)MDIM * KDIM];   // 64 MB
__device__ __half d_Wh[(size_t)NDIM * KDIM];   // 32 MB

// ---------------- PTX helpers ----------------
__device__ __forceinline__ uint32_t smem_u32(const void* p) {
    uint32_t a;
    asm("{ .reg .u64 t; cvta.to.shared.u64 t, %1; cvt.u32.u64 %0, t; }" : "=r"(a) : "l"(p));
    return a;
}

__device__ __forceinline__ void cp_async_16(uint32_t smem_dst, const void* gptr) {
    asm volatile("cp.async.cg.shared.global [%0], [%1], 16;"
                 :: "r"(smem_dst), "l"(__cvta_generic_to_global(gptr)) : "memory");
}

#define CP_COMMIT() asm volatile("cp.async.commit_group;" ::: "memory")
#define CP_WAIT(n)  asm volatile("cp.async.wait_group %0;" :: "n"(n) : "memory")

#define LDSM4(r0, r1, r2, r3, addr) \
    asm volatile("ldmatrix.sync.aligned.m8n8.x4.shared.b16 {%0,%1,%2,%3}, [%4];" \
        : "=r"(r0), "=r"(r1), "=r"(r2), "=r"(r3) : "r"(addr))

#define MMA16816(c, a0, a1, a2, a3, b0, b1) \
    asm volatile("mma.sync.aligned.m16n8k16.row.col.f32.f16.f16.f32 " \
        "{%0,%1,%2,%3}, {%4,%5,%6,%7}, {%8,%9}, {%0,%1,%2,%3};" \
        : "+f"((c)[0]), "+f"((c)[1]), "+f"((c)[2]), "+f"((c)[3]) \
        : "r"(a0), "r"(a1), "r"(a2), "r"(a3), "r"(b0), "r"(b1))

// swizzled byte offset within a 128B-row tile: col ^= (row&7)<<4
__device__ __forceinline__ uint32_t swz(int row, int colbyte) {
    return (uint32_t)(row * 128 + (colbyte ^ ((row & 7) << 4)));
}

// ---------------- pre-pass kernels ----------------
__global__ void convertA_kernel(const float* __restrict__ x) {
    size_t i = (size_t)blockIdx.x * blockDim.x + threadIdx.x;  // one float4
    float4 v = reinterpret_cast<const float4*>(x)[i];
    __half2* dst = reinterpret_cast<__half2*>(d_Ah);
    dst[2 * i + 0] = __floats2half2_rn(v.x, v.y);
    dst[2 * i + 1] = __floats2half2_rn(v.z, v.w);
}

__global__ void dequantW_kernel(const int* __restrict__ qw, const float* __restrict__ sc,
                                const int* __restrict__ qz) {
    size_t idx = (size_t)blockIdx.x * blockDim.x + threadIdx.x;  // one packed byte
    int b = qw[idx];
    int g = (int)(idx >> 6);                 // flat group n*32+qr
    int zp = qz[g >> 1];
    int z = (g & 1) ? ((zp >> 4) & 15) : (zp & 15);
    float s = sc[g];
    float lo = (float)((b & 15) - z) * s;
    float hi = (float)(((b >> 4) & 15) - z) * s;
    reinterpret_cast<__half2*>(d_Wh)[idx] = __floats2half2_rn(lo, hi);
}

// ---------------- GEMM kernel (mma.sync m16n8k16, TN) ----------------
__global__ void __launch_bounds__(GEMM_THREADS)
gemm_kernel(const float* __restrict__ bias, float* __restrict__ out) {
    extern __shared__ char smem[];
    const uint32_t sb = smem_u32(smem);
    const int tid = threadIdx.x;
    const int wid = tid >> 5;
    const int lane = tid & 31;

    const int n0 = blockIdx.x * BN;
    const int m0 = blockIdx.y * BM;

    // warp layout: 4(M) x 2(N); warp tile 32x64
    const int wm = wid & 3;
    const int wn = wid >> 2;

    const __half* Abase = d_Ah + (size_t)m0 * KDIM;
    const __half* Bbase = d_Wh + (size_t)n0 * KDIM;

    // ---- per-lane ldmatrix base addresses (stage 0, k-chunk 0) ----
    // A frag rows wm*32 + {0..15, 16..31}, col halves (lane>>4)*8 => bytes (lane>>4)*16
    const int lr = lane & 15;
    const int lc = (lane >> 4) * 16;
    uint32_t aA0 = sb + swz(wm * 32 + lr,      lc);
    uint32_t aA1 = sb + swz(wm * 32 + 16 + lr, lc);
    uint32_t aB0 = sb + 16384u + swz(wn * 64 + 0  + lr, lc);
    uint32_t aB1 = sb + 16384u + swz(wn * 64 + 16 + lr, lc);
    uint32_t aB2 = sb + 16384u + swz(wn * 64 + 32 + lr, lc);
    uint32_t aB3 = sb + 16384u + swz(wn * 64 + 48 + lr, lc);

    float acc[2][8][4];
    #pragma unroll
    for (int mi = 0; mi < 2; mi++)
        #pragma unroll
        for (int ni = 0; ni < 8; ni++)
            #pragma unroll
            for (int q = 0; q < 4; q++) acc[mi][ni][q] = 0.0f;

    // ---- producer: 8 x 16B chunks per thread per stage ----
    auto issue_stage = [&](int kt, int slot) {
        const uint32_t stb = sb + (uint32_t)slot * STAGE_BYTES;
        const int k0 = kt * BK;
        #pragma unroll
        for (int i = 0; i < 8; i++) {
            const int c = tid + i * 256;
            const int isB = c >> 10;
            const int cc = c & 1023;
            const int row = cc >> 3;
            const int j = cc & 7;
            const __half* g = (isB ? Bbase : Abase) + (size_t)row * KDIM + k0 + j * 8;
            cp_async_16(stb + (isB ? 16384u : 0u) + swz(row, j * 16), g);
        }
    };

    // prologue: stages 0..STAGES-2
    #pragma unroll
    for (int s = 0; s < STAGES - 1; s++) { issue_stage(s, s); CP_COMMIT(); }

    for (int kt = 0; kt < KTILES; ++kt) {
        CP_WAIT(STAGES - 2);
        __syncthreads();

        const int nxt = kt + STAGES - 1;
        if (nxt < KTILES) issue_stage(nxt, nxt % STAGES);
        CP_COMMIT();

        const uint32_t stoff = (uint32_t)(kt % STAGES) * STAGE_BYTES;
        #pragma unroll
        for (int kk = 0; kk < 4; kk++) {
            const uint32_t kx = (uint32_t)(kk << 5);
            uint32_t a[8], b[16];
            LDSM4(a[0], a[1], a[2], a[3], (aA0 + stoff) ^ kx);
            LDSM4(a[4], a[5], a[6], a[7], (aA1 + stoff) ^ kx);
            LDSM4(b[0], b[1], b[2], b[3],  (aB0 + stoff) ^ kx);
            LDSM4(b[4], b[5], b[6], b[7],  (aB1 + stoff) ^ kx);
            LDSM4(b[8], b[9], b[10], b[11], (aB2 + stoff) ^ kx);
            LDSM4(b[12], b[13], b[14], b[15], (aB3 + stoff) ^ kx);
            #pragma unroll
            for (int mi = 0; mi < 2; mi++) {
                #pragma unroll
                for (int t = 0; t < 4; t++) {
                    MMA16816(acc[mi][2 * t + 0], a[mi * 4 + 0], a[mi * 4 + 1],
                             a[mi * 4 + 2], a[mi * 4 + 3], b[t * 4 + 0], b[t * 4 + 2]);
                    MMA16816(acc[mi][2 * t + 1], a[mi * 4 + 0], a[mi * 4 + 1],
                             a[mi * 4 + 2], a[mi * 4 + 3], b[t * 4 + 1], b[t * 4 + 3]);
                }
            }
        }
    }

    // ---- epilogue: bias + float2 stores (32B per quad -> full sectors) ----
    const int r = lane >> 2;
    const int cpair = (lane & 3) * 2;
    const int mbase = m0 + wm * 32;
    const int nbase = n0 + wn * 64;
    #pragma unroll
    for (int mi = 0; mi < 2; mi++) {
        const int row0 = mbase + mi * 16 + r;
        const int row1 = row0 + 8;
        float* o0 = out + (size_t)row0 * NDIM;
        float* o1 = out + (size_t)row1 * NDIM;
        #pragma unroll
        for (int ni = 0; ni < 8; ni++) {
            const int col = nbase + ni * 8 + cpair;
            const float bx = __ldg(&bias[col]);
            const float by = __ldg(&bias[col + 1]);
            float2 v0 = make_float2(acc[mi][ni][0] + bx, acc[mi][ni][1] + by);
            float2 v1 = make_float2(acc[mi][ni][2] + bx, acc[mi][ni][3] + by);
            *reinterpret_cast<float2*>(o0 + col) = v0;
            *reinterpret_cast<float2*>(o1 + col) = v1;
        }
    }
}

// ---------------- launch ----------------
extern "C" void kernel_launch(void* const* d_in, const int* in_sizes, int n_in,
                              void* d_out, int out_size) {
    const float* x       = (const float*)d_in[0];
    const int*   qweight = (const int*)d_in[1];
    const float* scales  = (const float*)d_in[2];
    const int*   qzeros  = (const int*)d_in[3];
    const float* bias    = (const float*)d_in[4];
    float* out = (float*)d_out;

    convertA_kernel<<<(int)((size_t)MDIM * KDIM / 4 / 256), 256>>>(x);
    dequantW_kernel<<<(int)((size_t)NDIM * GROUPS * BLOB / 256), 256>>>(qweight, scales, qzeros);

    cudaFuncSetAttribute(gemm_kernel, cudaFuncAttributeMaxDynamicSharedMemorySize, SMEM_TOTAL);
    gemm_kernel<<<dim3(NDIM / BN, MDIM / BM), GEMM_THREADS, SMEM_TOTAL>>>(bias, out);
}

// round 3
// speedup vs baseline: 1.0532x; 1.0532x over previous
#include <cuda_runtime.h>
#include <cuda_fp16.h>
#include <cstdint>

// ---------------- problem dims (fixed) ----------------
#define MDIM 8192
#define NDIM 4096
#define KDIM 4096
#define GROUPS 32
#define BLOB  64

// ---------------- GEMM tiling ----------------
#define BM 256
#define BN 128
#define BK 64            // halves per k-tile (128 bytes per row)
#define STAGES 4
#define GEMM_THREADS 256
#define KTILES (KDIM / BK)            // 64
#define A_STAGE_BYTES (BM * 128)      // 32KB
#define B_STAGE_BYTES (BN * 128)      // 16KB
#define STAGE_BYTES (A_STAGE_BYTES + B_STAGE_BYTES)   // 48KB
#define SMEM_TOTAL (STAGES * STAGE_BYTES)             // 192KB

// fp16 scratch (static device globals; no allocations)
__device__ __half d_Ah[(size_t)MDIM * KDIM];   // 64 MB
__device__ __half d_Wh[(size_t)NDIM * KDIM];   // 32 MB

// ---------------- PTX helpers ----------------
__device__ __forceinline__ uint32_t smem_u32(const void* p) {
    uint32_t a;
    asm("{ .reg .u64 t; cvta.to.shared.u64 t, %1; cvt.u32.u64 %0, t; }" : "=r"(a) : "l"(p));
    return a;
}

__device__ __forceinline__ void cp_async_16(uint32_t smem_dst, const void* gptr) {
    asm volatile("cp.async.cg.shared.global [%0], [%1], 16;"
                 :: "r"(smem_dst), "l"(__cvta_generic_to_global(gptr)) : "memory");
}

#define CP_COMMIT() asm volatile("cp.async.commit_group;" ::: "memory")
#define CP_WAIT(n)  asm volatile("cp.async.wait_group %0;" :: "n"(n) : "memory")

#define LDSM4(r0, r1, r2, r3, addr) \
    asm volatile("ldmatrix.sync.aligned.m8n8.x4.shared.b16 {%0,%1,%2,%3}, [%4];" \
        : "=r"(r0), "=r"(r1), "=r"(r2), "=r"(r3) : "r"(addr))

#define MMA16816(c, a0, a1, a2, a3, b0, b1) \
    asm volatile("mma.sync.aligned.m16n8k16.row.col.f32.f16.f16.f32 " \
        "{%0,%1,%2,%3}, {%4,%5,%6,%7}, {%8,%9}, {%0,%1,%2,%3};" \
        : "+f"((c)[0]), "+f"((c)[1]), "+f"((c)[2]), "+f"((c)[3]) \
        : "r"(a0), "r"(a1), "r"(a2), "r"(a3), "r"(b0), "r"(b1))

// swizzled byte offset within a 128B-row tile: col ^= (row&7)<<4
__device__ __forceinline__ uint32_t swz(int row, int colbyte) {
    return (uint32_t)(row * 128 + (colbyte ^ ((row & 7) << 4)));
}

// ---------------- pre-pass kernels ----------------
__global__ void convertA_kernel(const float* __restrict__ x) {
    size_t i = (size_t)blockIdx.x * blockDim.x + threadIdx.x;  // one float4
    float4 v = reinterpret_cast<const float4*>(x)[i];
    __half2* dst = reinterpret_cast<__half2*>(d_Ah);
    dst[2 * i + 0] = __floats2half2_rn(v.x, v.y);
    dst[2 * i + 1] = __floats2half2_rn(v.z, v.w);
}

__global__ void dequantW_kernel(const int* __restrict__ qw, const float* __restrict__ sc,
                                const int* __restrict__ qz) {
    size_t idx = (size_t)blockIdx.x * blockDim.x + threadIdx.x;  // one packed byte
    int b = qw[idx];
    int g = (int)(idx >> 6);                 // flat group n*32+qr
    int zp = qz[g >> 1];
    int z = (g & 1) ? ((zp >> 4) & 15) : (zp & 15);
    float s = sc[g];
    float lo = (float)((b & 15) - z) * s;
    float hi = (float)(((b >> 4) & 15) - z) * s;
    reinterpret_cast<__half2*>(d_Wh)[idx] = __floats2half2_rn(lo, hi);
}

// ---------------- GEMM kernel (mma.sync m16n8k16, TN, warp tile 64x64) ----------------
__global__ void __launch_bounds__(GEMM_THREADS, 1)
gemm_kernel(const float* __restrict__ bias, float* __restrict__ out) {
    extern __shared__ char smem[];
    const uint32_t sb = smem_u32(smem);
    const int tid = threadIdx.x;
    const int wid = tid >> 5;
    const int lane = tid & 31;

    const int n0 = blockIdx.x * BN;
    const int m0 = blockIdx.y * BM;

    // warp layout: 4(M) x 2(N); warp tile 64x64
    const int wm = wid & 3;
    const int wn = wid >> 2;

    const __half* Abase = d_Ah + (size_t)m0 * KDIM;
    const __half* Bbase = d_Wh + (size_t)n0 * KDIM;

    // ---- per-lane ldmatrix base addresses (stage 0, k-chunk 0) ----
    const int lr = lane & 15;
    const int lc = (lane >> 4) * 16;
    uint32_t aA[4], aB[4];
    #pragma unroll
    for (int i = 0; i < 4; i++) {
        aA[i] = sb + swz(wm * 64 + i * 16 + lr, lc);
        aB[i] = sb + (uint32_t)A_STAGE_BYTES + swz(wn * 64 + i * 16 + lr, lc);
    }

    float acc[4][8][4];
    #pragma unroll
    for (int mi = 0; mi < 4; mi++)
        #pragma unroll
        for (int ni = 0; ni < 8; ni++)
            #pragma unroll
            for (int q = 0; q < 4; q++) acc[mi][ni][q] = 0.0f;

    // ---- producer: 12 x 16B chunks per thread per stage (A: 2048, B: 1024) ----
    auto issue_stage = [&](int kt, int slot) {
        const uint32_t stb = sb + (uint32_t)slot * STAGE_BYTES;
        const int k0 = kt * BK;
        #pragma unroll
        for (int i = 0; i < 12; i++) {
            const int c = tid + i * 256;
            const int isB = (c >= 2048) ? 1 : 0;
            const int cc = c - isB * 2048;
            const int row = cc >> 3;
            const int j = cc & 7;
            const __half* g = (isB ? Bbase : Abase) + (size_t)row * KDIM + k0 + j * 8;
            cp_async_16(stb + (uint32_t)isB * A_STAGE_BYTES + swz(row, j * 16), g);
        }
    };

    // prologue: stages 0..STAGES-2
    #pragma unroll
    for (int s = 0; s < STAGES - 1; s++) { issue_stage(s, s); CP_COMMIT(); }

    for (int kt = 0; kt < KTILES; ++kt) {
        CP_WAIT(STAGES - 2);
        __syncthreads();

        const int nxt = kt + STAGES - 1;
        if (nxt < KTILES) issue_stage(nxt, nxt % STAGES);
        CP_COMMIT();

        const uint32_t stoff = (uint32_t)(kt % STAGES) * STAGE_BYTES;
        #pragma unroll
        for (int kk = 0; kk < 4; kk++) {
            const uint32_t kx = (uint32_t)(kk << 5);
            uint32_t a[16], b[16];
            #pragma unroll
            for (int i = 0; i < 4; i++)
                LDSM4(a[i * 4 + 0], a[i * 4 + 1], a[i * 4 + 2], a[i * 4 + 3],
                      (aA[i] + stoff) ^ kx);
            #pragma unroll
            for (int i = 0; i < 4; i++)
                LDSM4(b[i * 4 + 0], b[i * 4 + 1], b[i * 4 + 2], b[i * 4 + 3],
                      (aB[i] + stoff) ^ kx);
            #pragma unroll
            for (int mi = 0; mi < 4; mi++) {
                #pragma unroll
                for (int t = 0; t < 4; t++) {
                    MMA16816(acc[mi][2 * t + 0], a[mi * 4 + 0], a[mi * 4 + 1],
                             a[mi * 4 + 2], a[mi * 4 + 3], b[t * 4 + 0], b[t * 4 + 2]);
                    MMA16816(acc[mi][2 * t + 1], a[mi * 4 + 0], a[mi * 4 + 1],
                             a[mi * 4 + 2], a[mi * 4 + 3], b[t * 4 + 1], b[t * 4 + 3]);
                }
            }
        }
    }

    // ---- epilogue: bias + float2 stores (32B per quad -> full sectors) ----
    const int r = lane >> 2;
    const int cpair = (lane & 3) * 2;
    const int mbase = m0 + wm * 64;
    const int nbase = n0 + wn * 64;
    float bx[8], by[8];
    #pragma unroll
    for (int ni = 0; ni < 8; ni++) {
        bx[ni] = __ldg(&bias[nbase + ni * 8 + cpair]);
        by[ni] = __ldg(&bias[nbase + ni * 8 + cpair + 1]);
    }
    #pragma unroll
    for (int mi = 0; mi < 4; mi++) {
        const int row0 = mbase + mi * 16 + r;
        float* o0 = out + (size_t)row0 * NDIM;
        float* o1 = out + (size_t)(row0 + 8) * NDIM;
        #pragma unroll
        for (int ni = 0; ni < 8; ni++) {
            const int col = nbase + ni * 8 + cpair;
            *reinterpret_cast<float2*>(o0 + col) =
                make_float2(acc[mi][ni][0] + bx[ni], acc[mi][ni][1] + by[ni]);
            *reinterpret_cast<float2*>(o1 + col) =
                make_float2(acc[mi][ni][2] + bx[ni], acc[mi][ni][3] + by[ni]);
        }
    }
}

// ---------------- launch ----------------
extern "C" void kernel_launch(void* const* d_in, const int* in_sizes, int n_in,
                              void* d_out, int out_size) {
    const float* x       = (const float*)d_in[0];
    const int*   qweight = (const int*)d_in[1];
    const float* scales  = (const float*)d_in[2];
    const int*   qzeros  = (const int*)d_in[3];
    const float* bias    = (const float*)d_in[4];
    float* out = (float*)d_out;

    convertA_kernel<<<(int)((size_t)MDIM * KDIM / 4 / 256), 256>>>(x);
    dequantW_kernel<<<(int)((size_t)NDIM * GROUPS * BLOB / 256), 256>>>(qweight, scales, qzeros);

    cudaFuncSetAttribute(gemm_kernel, cudaFuncAttributeMaxDynamicSharedMemorySize, SMEM_TOTAL);
    gemm_kernel<<<dim3(NDIM / BN, MDIM / BM), GEMM_THREADS, SMEM_TOTAL>>>(bias, out);
}

// round 5
// speedup vs baseline: 1.3838x; 1.3138x over previous
#include <cuda_runtime.h>
#include <cuda_fp16.h>
#include <cstdint>

// ---------------- problem dims (fixed) ----------------
#define MDIM 8192
#define NDIM 4096
#define KDIM 4096
#define GROUPS 32
#define BLOB  64

// ---------------- GEMM tiling ----------------
#define BM 256
#define BN 128
#define BK 64            // halves per k-tile (128 bytes per row)
#define STAGES 4
#define GEMM_THREADS 256
#define KTILES (KDIM / BK)            // 64
#define A_STAGE_BYTES (BM * 128)      // 32KB
#define B_STAGE_BYTES (BN * 128)      // 16KB
#define STAGE_BYTES (A_STAGE_BYTES + B_STAGE_BYTES)   // 48KB
#define SMEM_TOTAL (STAGES * STAGE_BYTES)             // 192KB

// fp16 scratch (static device globals; no allocations)
__device__ __half d_Ah[(size_t)MDIM * KDIM];   // 64 MB
__device__ __half d_Wh[(size_t)NDIM * KDIM];   // 32 MB

// ---------------- PTX helpers ----------------
__device__ __forceinline__ uint32_t smem_u32(const void* p) {
    uint32_t a;
    asm("{ .reg .u64 t; cvta.to.shared.u64 t, %1; cvt.u32.u64 %0, t; }" : "=r"(a) : "l"(p));
    return a;
}

__device__ __forceinline__ void cp_async_16(uint32_t smem_dst, const void* gptr) {
    asm volatile("cp.async.cg.shared.global [%0], [%1], 16;"
                 :: "r"(smem_dst), "l"(__cvta_generic_to_global(gptr)) : "memory");
}

#define CP_COMMIT() asm volatile("cp.async.commit_group;" ::: "memory")
#define CP_WAIT(n)  asm volatile("cp.async.wait_group %0;" :: "n"(n) : "memory")

#define LDSM4(r0, r1, r2, r3, addr) \
    asm volatile("ldmatrix.sync.aligned.m8n8.x4.shared.b16 {%0,%1,%2,%3}, [%4];" \
        : "=r"(r0), "=r"(r1), "=r"(r2), "=r"(r3) : "r"(addr))

#define MMA16816(c, a0, a1, a2, a3, b0, b1) \
    asm volatile("mma.sync.aligned.m16n8k16.row.col.f32.f16.f16.f32 " \
        "{%0,%1,%2,%3}, {%4,%5,%6,%7}, {%8,%9}, {%0,%1,%2,%3};" \
        : "+f"((c)[0]), "+f"((c)[1]), "+f"((c)[2]), "+f"((c)[3]) \
        : "r"(a0), "r"(a1), "r"(a2), "r"(a3), "r"(b0), "r"(b1))

// swizzled byte offset within a 128B-row tile: col ^= (row&7)<<4
__device__ __forceinline__ uint32_t swz(int row, int colbyte) {
    return (uint32_t)(row * 128 + (colbyte ^ ((row & 7) << 4)));
}

// ---------------- pre-pass kernels (MLP=4) ----------------
__global__ void convertA_kernel(const float* __restrict__ x) {
    const size_t stride = (size_t)gridDim.x * blockDim.x;
    size_t i = (size_t)blockIdx.x * blockDim.x + threadIdx.x;
    const float4* src = reinterpret_cast<const float4*>(x);
    __half2* dst = reinterpret_cast<__half2*>(d_Ah);
    float4 v0 = src[i];
    float4 v1 = src[i + stride];
    float4 v2 = src[i + 2 * stride];
    float4 v3 = src[i + 3 * stride];
    dst[2 * i + 0] = __floats2half2_rn(v0.x, v0.y);
    dst[2 * i + 1] = __floats2half2_rn(v0.z, v0.w);
    dst[2 * (i + stride) + 0] = __floats2half2_rn(v1.x, v1.y);
    dst[2 * (i + stride) + 1] = __floats2half2_rn(v1.z, v1.w);
    dst[2 * (i + 2 * stride) + 0] = __floats2half2_rn(v2.x, v2.y);
    dst[2 * (i + 2 * stride) + 1] = __floats2half2_rn(v2.z, v2.w);
    dst[2 * (i + 3 * stride) + 0] = __floats2half2_rn(v3.x, v3.y);
    dst[2 * (i + 3 * stride) + 1] = __floats2half2_rn(v3.z, v3.w);
}

// one int4 (4 packed bytes) per thread; all 4 land in the same group
__global__ void dequantW_kernel(const int* __restrict__ qw, const float* __restrict__ sc,
                                const int* __restrict__ qz) {
    size_t t = (size_t)blockIdx.x * blockDim.x + threadIdx.x;
    int4 b4 = reinterpret_cast<const int4*>(qw)[t];
    size_t idx = t * 4;
    int g = (int)(idx >> 6);                 // flat group n*32+qr (64 bytes per group)
    int zp = qz[g >> 1];
    int z = (g & 1) ? ((zp >> 4) & 15) : (zp & 15);
    float s = sc[g];
    __half2 h[4];
    int bb[4] = {b4.x, b4.y, b4.z, b4.w};
    #pragma unroll
    for (int q = 0; q < 4; q++) {
        float lo = (float)((bb[q] & 15) - z) * s;
        float hi = (float)(((bb[q] >> 4) & 15) - z) * s;
        h[q] = __floats2half2_rn(lo, hi);
    }
    reinterpret_cast<uint4*>(d_Wh)[t] = *reinterpret_cast<uint4*>(h);
}

// ---------------- GEMM kernel (mma.sync m16n8k16, TN, warp tile 64x64, pipelined) ----------------
__global__ void __launch_bounds__(GEMM_THREADS, 1)
gemm_kernel(const float* __restrict__ bias, float* __restrict__ out) {
    extern __shared__ char smem[];
    const uint32_t sb = smem_u32(smem);
    const int tid = threadIdx.x;
    const int wid = tid >> 5;
    const int lane = tid & 31;

    const int n0 = blockIdx.x * BN;
    const int m0 = blockIdx.y * BM;

    // warp layout: 4(M) x 2(N); warp tile 64x64
    const int wm = wid & 3;
    const int wn = wid >> 2;

    const __half* Abase = d_Ah + (size_t)m0 * KDIM;
    const __half* Bbase = d_Wh + (size_t)n0 * KDIM;

    // ---- per-lane ldmatrix base addresses (stage 0, k-chunk 0) ----
    const int lr = lane & 15;
    const int lc = (lane >> 4) * 16;
    uint32_t aA[4], aB[4];
    #pragma unroll
    for (int i = 0; i < 4; i++) {
        aA[i] = sb + swz(wm * 64 + i * 16 + lr, lc);
        aB[i] = sb + (uint32_t)A_STAGE_BYTES + swz(wn * 64 + i * 16 + lr, lc);
    }

    float acc[4][8][4];
    #pragma unroll
    for (int mi = 0; mi < 4; mi++)
        #pragma unroll
        for (int ni = 0; ni < 8; ni++)
            #pragma unroll
            for (int q = 0; q < 4; q++) acc[mi][ni][q] = 0.0f;

    // producer slice p (3 of 12 chunks) for k-tile kt into stage slot
    auto issue_part = [&](int kt, int slot, int p) {
        const uint32_t stb = sb + (uint32_t)slot * STAGE_BYTES;
        const int k0 = kt * BK;
        #pragma unroll
        for (int q = 0; q < 3; q++) {
            const int c = tid + (3 * p + q) * 256;
            const int isB = (c >= 2048) ? 1 : 0;
            const int cc = c - isB * 2048;
            const int row = cc >> 3;
            const int j = cc & 7;
            const __half* g = (isB ? Bbase : Abase) + (size_t)row * KDIM + k0 + j * 8;
            cp_async_16(stb + (uint32_t)isB * A_STAGE_BYTES + swz(row, j * 16), g);
        }
    };

    uint32_t afr[2][16], bfr[2][16];
    // interleaved A/B ldmatrix for (stage offset, kk) into buffer buf
    auto load_frags = [&](uint32_t stoff, int kk, int buf) {
        const uint32_t kx = (uint32_t)(kk << 5);
        #pragma unroll
        for (int i = 0; i < 4; i++) {
            LDSM4(afr[buf][i * 4 + 0], afr[buf][i * 4 + 1], afr[buf][i * 4 + 2],
                  afr[buf][i * 4 + 3], (aA[i] + stoff) ^ kx);
            LDSM4(bfr[buf][i * 4 + 0], bfr[buf][i * 4 + 1], bfr[buf][i * 4 + 2],
                  bfr[buf][i * 4 + 3], (aB[i] + stoff) ^ kx);
        }
    };

    auto do_mma = [&](int buf) {
        #pragma unroll
        for (int mi = 0; mi < 4; mi++) {
            #pragma unroll
            for (int t = 0; t < 4; t++) {
                MMA16816(acc[mi][2 * t + 0], afr[buf][mi * 4 + 0], afr[buf][mi * 4 + 1],
                         afr[buf][mi * 4 + 2], afr[buf][mi * 4 + 3],
                         bfr[buf][t * 4 + 0], bfr[buf][t * 4 + 2]);
                MMA16816(acc[mi][2 * t + 1], afr[buf][mi * 4 + 0], afr[buf][mi * 4 + 1],
                         afr[buf][mi * 4 + 2], afr[buf][mi * 4 + 3],
                         bfr[buf][t * 4 + 1], bfr[buf][t * 4 + 3]);
            }
        }
    };

    // prologue: fill stages 0..2
    #pragma unroll
    for (int s = 0; s < STAGES - 1; s++) {
        #pragma unroll
        for (int p = 0; p < 4; p++) issue_part(s, s, p);
        CP_COMMIT();
    }
    CP_WAIT(STAGES - 2);
    __syncthreads();
    load_frags(0, 0, 0);

    for (int kt = 0; kt < KTILES; ++kt) {
        const uint32_t stoff = (uint32_t)(kt & 3) * STAGE_BYTES;
        const int nxt = kt + STAGES - 1;
        const int nslot = nxt & 3;
        const bool refill = (nxt < KTILES);
        #pragma unroll
        for (int kk = 0; kk < 4; kk++) {
            if (refill) issue_part(nxt, nslot, kk);  // spread producer issue
            if (kk < 3) {
                load_frags(stoff, kk + 1, (kk + 1) & 1);  // prefetch next frags
            } else {
                CP_COMMIT();
                CP_WAIT(STAGES - 2);
            }
            do_mma(kk & 1);
        }
        __syncthreads();
        if (kt + 1 < KTILES)
            load_frags((uint32_t)((kt + 1) & 3) * STAGE_BYTES, 0, 0);
    }

    // ---- epilogue: bias + float2 stores (32B per quad -> full sectors) ----
    const int r = lane >> 2;
    const int cpair = (lane & 3) * 2;
    const int mbase = m0 + wm * 64;
    const int nbase = n0 + wn * 64;
    float bx[8], by[8];
    #pragma unroll
    for (int ni = 0; ni < 8; ni++) {
        bx[ni] = __ldg(&bias[nbase + ni * 8 + cpair]);
        by[ni] = __ldg(&bias[nbase + ni * 8 + cpair + 1]);
    }
    #pragma unroll
    for (int mi = 0; mi < 4; mi++) {
        const int row0 = mbase + mi * 16 + r;
        float* o0 = out + (size_t)row0 * NDIM;
        float* o1 = out + (size_t)(row0 + 8) * NDIM;
        #pragma unroll
        for (int ni = 0; ni < 8; ni++) {
            const int col = nbase + ni * 8 + cpair;
            *reinterpret_cast<float2*>(o0 + col) =
                make_float2(acc[mi][ni][0] + bx[ni], acc[mi][ni][1] + by[ni]);
            *reinterpret_cast<float2*>(o1 + col) =
                make_float2(acc[mi][ni][2] + bx[ni], acc[mi][ni][3] + by[ni]);
        }
    }
}

// ---------------- launch ----------------
extern "C" void kernel_launch(void* const* d_in, const int* in_sizes, int n_in,
                              void* d_out, int out_size) {
    const float* x       = (const float*)d_in[0];
    const int*   qweight = (const int*)d_in[1];
    const float* scales  = (const float*)d_in[2];
    const int*   qzeros  = (const int*)d_in[3];
    const float* bias    = (const float*)d_in[4];
    float* out = (float*)d_out;

    // x -> fp16: 8388608 float4s, 4 per thread
    convertA_kernel<<<8192, 256>>>(x);
    // dequant: 2097152 int4s, 1 per thread
    dequantW_kernel<<<8192, 256>>>(qweight, scales, qzeros);

    cudaFuncSetAttribute(gemm_kernel, cudaFuncAttributeMaxDynamicSharedMemorySize, SMEM_TOTAL);
    gemm_kernel<<<dim3(NDIM / BN, MDIM / BM), GEMM_THREADS, SMEM_TOTAL>>>(bias, out);
}